// round 10
// baseline (speedup 1.0000x reference)
#include <cuda_runtime.h>
#include <cuda_bf16.h>
#include <math.h>

#define N_GAUSS 2048
#define HEIGHT  192
#define WIDTH   192
#define HW      (HEIGHT*WIDTH)
#define ALPHA_MAX 0.999f
#define ALPHA_MIN (1.0f/255.0f)
#define NSEG    8
#define SEG     (N_GAUSS / NSEG)   // 256

// Depth-sorted gaussian data
__device__ float4 g_A[N_GAUSS];  // mx, my, conic_a, conic_b
__device__ float4 g_B[N_GAUSS];  // conic_c, opacity, col_r, col_g
__device__ float2 g_C[N_GAUSS];  // col_b, sigma_threshold (threshold used by cull build only)
__device__ float2 g_D[N_GAUSS];  // rx, ry : AABB half-extents
// Per-segment partial composites: (accR, accG, accB, T_seg)
__device__ float4 g_seg[NSEG][HW];

// ---------------------------------------------------------------------------
// Kernel 1: rank-by-counting sort, one warp per gaussian (unchanged; at its
// first-kernel floor). Order lexicographic (depth, index), ties by index.
// ---------------------------------------------------------------------------
__global__ void __launch_bounds__(256)
sort_scatter_kernel(const float* __restrict__ means2d,
                    const float* __restrict__ conics,
                    const float* __restrict__ colors,
                    const float* __restrict__ opacities,
                    const float* __restrict__ depths)
{
    __shared__ float sd[N_GAUSS];
    const int tid  = threadIdx.x;
    const int warp = tid >> 5, lane = tid & 31;
    const int gid  = blockIdx.x * 8 + warp;

    // Hoisted param loads (lane 0; overlaps staging + count latency).
    float p_mx, p_my, p_ca, p_cb, p_cc, p_op, p_cr, p_cg, p_cbl;
    if (lane == 0) {
        p_mx = means2d[2*gid + 0];
        p_my = means2d[2*gid + 1];
        p_ca = conics[3*gid + 0];
        p_cb = conics[3*gid + 1];
        p_cc = conics[3*gid + 2];
        p_op = opacities[gid];
        p_cr = colors[3*gid + 0];
        p_cg = colors[3*gid + 1];
        p_cbl= colors[3*gid + 2];
    }

    #pragma unroll
    for (int i = tid; i < N_GAUSS; i += 256)
        sd[i] = depths[i];
    __syncthreads();

    const float myd = sd[gid];
    int c = 0;
    #pragma unroll 16
    for (int k = 0; k < N_GAUSS / 32; ++k) {
        int i = k * 32 + lane;
        float d = sd[i];
        c += (d < myd) || ((d == myd) && (i < gid));
    }
    int rank = __reduce_add_sync(0xffffffffu, c);

    if (lane == 0) {
        // alpha >= 1/255  <=>  sigma <= log(255*op); margin keeps the AABB
        // cull conservative vs the exact in-walk check.
        float t = logf(255.0f * p_op) + 1e-4f;
        float det = p_ca * p_cc - p_cb * p_cb;
        float inv = 2.0f * fmaxf(t, 0.0f) / det;
        float rx = sqrtf(fmaxf(inv * p_cc, 0.0f)) + 1e-3f;
        float ry = sqrtf(fmaxf(inv * p_ca, 0.0f)) + 1e-3f;
        g_A[rank] = make_float4(p_mx, p_my, p_ca, p_cb);
        g_B[rank] = make_float4(p_cc, p_op, p_cr, p_cg);
        g_C[rank] = make_float2(p_cbl, t);
        g_D[rank] = make_float2(rx, ry);
    }
}

// ---------------------------------------------------------------------------
// Kernel 2: depth-segmented, per-warp strip-culled compositing with a
// BRANCHLESS survivor walk: alpha_eff = valid ? alpha : 0, composite
// unconditionally (zero alpha is an exact no-op). valid is the exact
// reference condition, so no sigma-threshold test is needed in the walk.
// ---------------------------------------------------------------------------
__global__ void __launch_bounds__(256)
render_seg_kernel()
{
    __shared__ float4 sA[SEG];
    __shared__ float4 sB[SEG];
    __shared__ float2 sC[SEG];
    __shared__ float2 sD[SEG];

    const int tid  = threadIdx.x;
    const int warp = tid >> 5, lane = tid & 31;
    const int seg  = blockIdx.z;
    const int base = seg * SEG;
    const int x = blockIdx.x * 16 + (tid & 15);
    const int y = blockIdx.y * 16 + (tid >> 4);
    const float px = (float)x + 0.5f;
    const float py = (float)y + 0.5f;

    const float sxmin = blockIdx.x * 16 + 0.5f;
    const float sxmax = blockIdx.x * 16 + 15.5f;
    const float symin = blockIdx.y * 16 + 2 * warp + 0.5f;
    const float symax = symin + 1.0f;

    {
        int i = tid;               // SEG == 256: one record per thread
        sA[i] = g_A[base + i];
        sB[i] = g_B[base + i];
        sC[i] = g_C[base + i];
        sD[i] = g_D[base + i];
    }
    __syncthreads();

    float T = 1.0f;
    float accr = 0.0f, accg = 0.0f, accb = 0.0f;

    for (int g = 0; g < SEG; g += 32) {
        // Lane-parallel cull of this 32-group against the warp's 16x2 strip.
        float4 a = sA[g + lane];
        float2 r = sD[g + lane];
        bool pred = (a.x - r.x <= sxmax) & (a.x + r.x >= sxmin) &
                    (a.y - r.y <= symax) & (a.y + r.y >= symin);
        unsigned mask = __ballot_sync(0xffffffffu, pred);

        // 2-wide, branchless, exactly-ordered walk over survivors.
        while (mask) {
            int j0 = g + (__ffs(mask) - 1);
            mask &= mask - 1;
            bool two = (mask != 0);
            int j1 = two ? (g + (__ffs(mask) - 1)) : j0;
            if (two) mask &= mask - 1;

            float4 A0 = sA[j0], A1 = sA[j1];
            float4 B0 = sB[j0], B1 = sB[j1];
            float2 C0 = sC[j0], C1 = sC[j1];

            float dx0 = px - A0.x, dy0 = py - A0.y;
            float dx1 = px - A1.x, dy1 = py - A1.y;
            float sg0 = 0.5f * (A0.z*dx0*dx0 + B0.x*dy0*dy0) + A0.w*dx0*dy0;
            float sg1 = 0.5f * (A1.z*dx1*dx1 + B1.x*dy1*dy1) + A1.w*dx1*dy1;
            float e0 = __expf(-sg0);
            float e1 = __expf(-sg1);

            float al0 = fminf(ALPHA_MAX, B0.y * e0);
            float al1 = fminf(ALPHA_MAX, B1.y * e1);
            // exact reference gate, as a select (no divergent branch)
            al0 = ((sg0 > 0.0f) & (al0 >= ALPHA_MIN)) ? al0 : 0.0f;
            al1 = ((sg1 > 0.0f) & (al1 >= ALPHA_MIN) & two) ? al1 : 0.0f;

            float w0 = T * al0;
            accr = fmaf(w0, B0.z, accr);
            accg = fmaf(w0, B0.w, accg);
            accb = fmaf(w0, C0.x, accb);
            T *= (1.0f - al0);

            float w1 = T * al1;
            accr = fmaf(w1, B1.z, accr);
            accg = fmaf(w1, B1.w, accg);
            accb = fmaf(w1, C1.x, accb);
            T *= (1.0f - al1);
        }
        // Segment-local early exit: dropped contributions bounded by
        // prefixT(<=1) * T_seg < 1e-7 absolute.
        if (!__ballot_sync(0xffffffffu, T >= 1e-7f)) break;
    }

    g_seg[seg][y * WIDTH + x] = make_float4(accr, accg, accb, T);
}

// ---------------------------------------------------------------------------
// Kernel 3: fold segments front-to-back + background.
// ---------------------------------------------------------------------------
__global__ void __launch_bounds__(256)
combine_kernel(const float* __restrict__ background, float* __restrict__ out)
{
    const int pix = blockIdx.x * 256 + threadIdx.x;
    float accr = 0.0f, accg = 0.0f, accb = 0.0f, T = 1.0f;
    #pragma unroll
    for (int s = 0; s < NSEG; ++s) {
        float4 v = g_seg[s][pix];
        accr = fmaf(T, v.x, accr);
        accg = fmaf(T, v.y, accg);
        accb = fmaf(T, v.z, accb);
        T *= v.w;
    }
    out[0 * HW + pix] = fmaf(background[0], T, accr);
    out[1 * HW + pix] = fmaf(background[1], T, accg);
    out[2 * HW + pix] = fmaf(background[2], T, accb);
}

// ---------------------------------------------------------------------------
extern "C" void kernel_launch(void* const* d_in, const int* in_sizes, int n_in,
                              void* d_out, int out_size)
{
    const float* means2d    = (const float*)d_in[0];
    const float* conics     = (const float*)d_in[1];
    const float* colors     = (const float*)d_in[2];
    const float* opacities  = (const float*)d_in[3];
    const float* depths     = (const float*)d_in[4];
    const float* background = (const float*)d_in[5];
    float* out = (float*)d_out;

    sort_scatter_kernel<<<N_GAUSS / 8, 256>>>(means2d, conics, colors, opacities, depths);
    dim3 grid(WIDTH / 16, HEIGHT / 16, NSEG);
    render_seg_kernel<<<grid, 256>>>();
    combine_kernel<<<HW / 256, 256>>>(background, out);
}

// round 11
// speedup vs baseline: 1.0152x; 1.0152x over previous
#include <cuda_runtime.h>
#include <cuda_bf16.h>
#include <math.h>

#define N_GAUSS 2048
#define HEIGHT  192
#define WIDTH   192
#define HW      (HEIGHT*WIDTH)
#define ALPHA_MAX 0.999f
#define ALPHA_MIN (1.0f/255.0f)
#define NSEG    8
#define SEG     (N_GAUSS / NSEG)   // 256

// Depth-sorted gaussian data (80 KB total -> L1/L2 resident)
__device__ float4 g_A[N_GAUSS];  // mx, my, conic_a, conic_b
__device__ float4 g_B[N_GAUSS];  // conic_c, opacity, col_r, col_g
__device__ float2 g_C[N_GAUSS];  // col_b, (unused pad)
__device__ float4 g_D[N_GAUSS];  // mx, my, rx, ry : packed cull record

// ---------------------------------------------------------------------------
// Kernel 1: rank-by-counting sort, one warp per gaussian (at its floor).
// Order lexicographic (depth, index), ties by index.
// ---------------------------------------------------------------------------
__global__ void __launch_bounds__(256)
sort_scatter_kernel(const float* __restrict__ means2d,
                    const float* __restrict__ conics,
                    const float* __restrict__ colors,
                    const float* __restrict__ opacities,
                    const float* __restrict__ depths)
{
    __shared__ float sd[N_GAUSS];
    const int tid  = threadIdx.x;
    const int warp = tid >> 5, lane = tid & 31;
    const int gid  = blockIdx.x * 8 + warp;

    // Hoisted param loads (lane 0; overlaps staging + count latency).
    float p_mx, p_my, p_ca, p_cb, p_cc, p_op, p_cr, p_cg, p_cbl;
    if (lane == 0) {
        p_mx = means2d[2*gid + 0];
        p_my = means2d[2*gid + 1];
        p_ca = conics[3*gid + 0];
        p_cb = conics[3*gid + 1];
        p_cc = conics[3*gid + 2];
        p_op = opacities[gid];
        p_cr = colors[3*gid + 0];
        p_cg = colors[3*gid + 1];
        p_cbl= colors[3*gid + 2];
    }

    #pragma unroll
    for (int i = tid; i < N_GAUSS; i += 256)
        sd[i] = depths[i];
    __syncthreads();

    const float myd = sd[gid];
    int c = 0;
    #pragma unroll 16
    for (int k = 0; k < N_GAUSS / 32; ++k) {
        int i = k * 32 + lane;
        float d = sd[i];
        c += (d < myd) || ((d == myd) && (i < gid));
    }
    int rank = __reduce_add_sync(0xffffffffu, c);

    if (lane == 0) {
        // alpha >= 1/255 <=> sigma <= log(255*op); margin keeps the AABB
        // cull conservative vs the exact in-walk gate.
        float t = logf(255.0f * p_op) + 1e-4f;
        float det = p_ca * p_cc - p_cb * p_cb;
        float inv = 2.0f * fmaxf(t, 0.0f) / det;
        float rx = sqrtf(fmaxf(inv * p_cc, 0.0f)) + 1e-3f;
        float ry = sqrtf(fmaxf(inv * p_ca, 0.0f)) + 1e-3f;
        g_A[rank] = make_float4(p_mx, p_my, p_ca, p_cb);
        g_B[rank] = make_float4(p_cc, p_op, p_cr, p_cg);
        g_C[rank] = make_float2(p_cbl, 0.0f);
        g_D[rank] = make_float4(p_mx, p_my, rx, ry);
    }
}

// ---------------------------------------------------------------------------
// Kernel 2 (fused render + combine): 8x8 px tile per block, 512 threads =
// 16 warps = 8 depth segments x 2 strips (8x4 px). Each warp walks its
// 256-gaussian segment for its strip (coalesced LDG.128 cull, warp-uniform
// broadcast survivor loads -> no smem staging). Partials land in smem; after
// ONE barrier, threads 0..63 fold the 8 segments in depth order + background
// and write out. No fences, no atomics, no global partial round-trip.
// ---------------------------------------------------------------------------
__global__ void __launch_bounds__(512)
render_fused_kernel(const float* __restrict__ background, float* __restrict__ out)
{
    __shared__ float4 smP[NSEG][64];   // (accR, accG, accB, T_seg) per pixel

    const int tid   = threadIdx.x;
    const int warp  = tid >> 5, lane = tid & 31;
    const int seg   = warp >> 1;            // 0..7
    const int strip = warp & 1;             // 0..1
    const int base  = seg * SEG;

    const int tx0 = blockIdx.x * 8;
    const int ty0 = blockIdx.y * 8;
    const int xl  = lane & 7;                // 0..7
    const int yl  = strip * 4 + (lane >> 3); // 0..7
    const float px = (float)(tx0 + xl) + 0.5f;
    const float py = (float)(ty0 + yl) + 0.5f;

    // This warp's 8x4 pixel-center strip bounds.
    const float sxmin = tx0 + 0.5f;
    const float sxmax = tx0 + 7.5f;
    const float symin = ty0 + strip * 4 + 0.5f;
    const float symax = symin + 3.0f;

    float T = 1.0f;
    float accr = 0.0f, accg = 0.0f, accb = 0.0f;

    for (int g = 0; g < SEG; g += 32) {
        // Coalesced cull: one LDG.128 per lane (mx,my,rx,ry).
        float4 d = g_D[base + g + lane];
        bool pred = (d.x - d.z <= sxmax) & (d.x + d.z >= sxmin) &
                    (d.y - d.w <= symax) & (d.y + d.w >= symin);
        unsigned mask = __ballot_sync(0xffffffffu, pred);

        // 2-wide, branchless, exactly-ordered walk (warp-uniform broadcasts).
        while (mask) {
            int j0 = base + g + (__ffs(mask) - 1);
            mask &= mask - 1;
            bool two = (mask != 0);
            int j1 = two ? (base + g + (__ffs(mask) - 1)) : j0;
            if (two) mask &= mask - 1;

            float4 A0 = g_A[j0], A1 = g_A[j1];
            float4 B0 = g_B[j0], B1 = g_B[j1];
            float2 C0 = g_C[j0], C1 = g_C[j1];

            float dx0 = px - A0.x, dy0 = py - A0.y;
            float dx1 = px - A1.x, dy1 = py - A1.y;
            float sg0 = 0.5f * (A0.z*dx0*dx0 + B0.x*dy0*dy0) + A0.w*dx0*dy0;
            float sg1 = 0.5f * (A1.z*dx1*dx1 + B1.x*dy1*dy1) + A1.w*dx1*dy1;
            float e0 = __expf(-sg0);
            float e1 = __expf(-sg1);

            float al0 = fminf(ALPHA_MAX, B0.y * e0);
            float al1 = fminf(ALPHA_MAX, B1.y * e1);
            // exact reference gate as selects (no divergent branches)
            al0 = ((sg0 > 0.0f) & (al0 >= ALPHA_MIN)) ? al0 : 0.0f;
            al1 = ((sg1 > 0.0f) & (al1 >= ALPHA_MIN) & two) ? al1 : 0.0f;

            float w0 = T * al0;
            accr = fmaf(w0, B0.z, accr);
            accg = fmaf(w0, B0.w, accg);
            accb = fmaf(w0, C0.x, accb);
            T *= (1.0f - al0);

            float w1 = T * al1;
            accr = fmaf(w1, B1.z, accr);
            accg = fmaf(w1, B1.w, accg);
            accb = fmaf(w1, C1.x, accb);
            T *= (1.0f - al1);
        }
        // Segment-local early exit: dropped contributions bounded by
        // prefixT(<=1) * T_seg < 1e-7 absolute.
        if (!__ballot_sync(0xffffffffu, T >= 1e-7f)) break;
    }

    smP[seg][yl * 8 + xl] = make_float4(accr, accg, accb, T);
    __syncthreads();

    // Fold the 8 segments front-to-back + background (threads 0..63).
    if (tid < 64) {
        float fr = 0.0f, fg = 0.0f, fb = 0.0f, fT = 1.0f;
        #pragma unroll
        for (int s = 0; s < NSEG; ++s) {
            float4 v = smP[s][tid];
            fr = fmaf(fT, v.x, fr);
            fg = fmaf(fT, v.y, fg);
            fb = fmaf(fT, v.z, fb);
            fT *= v.w;
        }
        const int pix = (ty0 + (tid >> 3)) * WIDTH + tx0 + (tid & 7);
        out[0 * HW + pix] = fmaf(background[0], fT, fr);
        out[1 * HW + pix] = fmaf(background[1], fT, fg);
        out[2 * HW + pix] = fmaf(background[2], fT, fb);
    }
}

// ---------------------------------------------------------------------------
extern "C" void kernel_launch(void* const* d_in, const int* in_sizes, int n_in,
                              void* d_out, int out_size)
{
    const float* means2d    = (const float*)d_in[0];
    const float* conics     = (const float*)d_in[1];
    const float* colors     = (const float*)d_in[2];
    const float* opacities  = (const float*)d_in[3];
    const float* depths     = (const float*)d_in[4];
    const float* background = (const float*)d_in[5];
    float* out = (float*)d_out;

    sort_scatter_kernel<<<N_GAUSS / 8, 256>>>(means2d, conics, colors, opacities, depths);
    dim3 grid(WIDTH / 8, HEIGHT / 8);
    render_fused_kernel<<<grid, 512>>>(background, out);
}

// round 12
// speedup vs baseline: 1.2903x; 1.2710x over previous
#include <cuda_runtime.h>
#include <cuda_bf16.h>
#include <math.h>

#define N_GAUSS 2048
#define HEIGHT  192
#define WIDTH   192
#define HW      (HEIGHT*WIDTH)
#define ALPHA_MAX 0.999f
#define ALPHA_MIN (1.0f/255.0f)
#define NSEG    8
#define SEG     (N_GAUSS / NSEG)   // 256
#define NGRP    (SEG / 32)         // 8 cull groups per segment

// Depth-sorted gaussian data (80 KB total -> L1/L2 resident)
__device__ float4 g_A[N_GAUSS];  // mx, my, conic_a, conic_b
__device__ float4 g_B[N_GAUSS];  // conic_c, opacity, col_r, col_g
__device__ float2 g_C[N_GAUSS];  // col_b, pad
__device__ float4 g_D[N_GAUSS];  // mx, my, rx, ry : packed cull record

// ---------------------------------------------------------------------------
// Kernel 1: rank-by-counting sort, one warp per gaussian.
// Order lexicographic (depth, index), ties by index.
// ---------------------------------------------------------------------------
__global__ void __launch_bounds__(256)
sort_scatter_kernel(const float* __restrict__ means2d,
                    const float* __restrict__ conics,
                    const float* __restrict__ colors,
                    const float* __restrict__ opacities,
                    const float* __restrict__ depths)
{
    __shared__ float sd[N_GAUSS];
    const int tid  = threadIdx.x;
    const int warp = tid >> 5, lane = tid & 31;
    const int gid  = blockIdx.x * 8 + warp;

    // Hoisted param loads (lane 0; overlaps staging + count latency).
    float p_mx, p_my, p_ca, p_cb, p_cc, p_op, p_cr, p_cg, p_cbl;
    if (lane == 0) {
        p_mx = means2d[2*gid + 0];
        p_my = means2d[2*gid + 1];
        p_ca = conics[3*gid + 0];
        p_cb = conics[3*gid + 1];
        p_cc = conics[3*gid + 2];
        p_op = opacities[gid];
        p_cr = colors[3*gid + 0];
        p_cg = colors[3*gid + 1];
        p_cbl= colors[3*gid + 2];
    }

    #pragma unroll
    for (int i = tid; i < N_GAUSS; i += 256)
        sd[i] = depths[i];
    __syncthreads();

    const float myd = sd[gid];
    int c = 0;
    #pragma unroll 16
    for (int k = 0; k < N_GAUSS / 32; ++k) {
        int i = k * 32 + lane;
        float d = sd[i];
        c += (d < myd) || ((d == myd) && (i < gid));
    }
    int rank = __reduce_add_sync(0xffffffffu, c);

    if (lane == 0) {
        // alpha >= 1/255 <=> sigma <= log(255*op); margin keeps the AABB
        // cull conservative vs the exact in-walk gate.
        float t = logf(255.0f * p_op) + 1e-4f;
        float det = p_ca * p_cc - p_cb * p_cb;
        float inv = 2.0f * fmaxf(t, 0.0f) / det;
        float rx = sqrtf(fmaxf(inv * p_cc, 0.0f)) + 1e-3f;
        float ry = sqrtf(fmaxf(inv * p_ca, 0.0f)) + 1e-3f;
        g_A[rank] = make_float4(p_mx, p_my, p_ca, p_cb);
        g_B[rank] = make_float4(p_cc, p_op, p_cr, p_cg);
        g_C[rank] = make_float2(p_cbl, 0.0f);
        g_D[rank] = make_float4(p_mx, p_my, rx, ry);
    }
}

// ---------------------------------------------------------------------------
// Kernel 2 (fused render + combine): 8x8 px tile per block, 512 threads =
// 16 warps = 8 depth segments x 2 strips (8x4 px). PHASE-SPLIT walk:
// all NGRP cull ballots are computed first in a fully unrolled, independent
// burst (8 overlapped LDG.128s), THEN survivors are walked. No early-exit
// ballot in the loop -> no serial chain, and the result is exact (no
// truncation). Partials fold in smem after one barrier.
// ---------------------------------------------------------------------------
__global__ void __launch_bounds__(512)
render_fused_kernel(const float* __restrict__ background, float* __restrict__ out)
{
    __shared__ float4 smP[NSEG][64];   // (accR, accG, accB, T_seg) per pixel

    const int tid   = threadIdx.x;
    const int warp  = tid >> 5, lane = tid & 31;
    const int seg   = warp >> 1;            // 0..7
    const int strip = warp & 1;             // 0..1
    const int base  = seg * SEG;

    const int tx0 = blockIdx.x * 8;
    const int ty0 = blockIdx.y * 8;
    const int xl  = lane & 7;                // 0..7
    const int yl  = strip * 4 + (lane >> 3); // 0..7
    const float px = (float)(tx0 + xl) + 0.5f;
    const float py = (float)(ty0 + yl) + 0.5f;

    // This warp's 8x4 pixel-center strip bounds.
    const float sxmin = tx0 + 0.5f;
    const float sxmax = tx0 + 7.5f;
    const float symin = ty0 + strip * 4 + 0.5f;
    const float symax = symin + 3.0f;

    // Phase 1: independent cull burst — all group ballots up front.
    unsigned masks[NGRP];
    #pragma unroll
    for (int k = 0; k < NGRP; ++k) {
        float4 d = g_D[base + k * 32 + lane];
        bool pred = (d.x - d.z <= sxmax) & (d.x + d.z >= sxmin) &
                    (d.y - d.w <= symax) & (d.y + d.w >= symin);
        masks[k] = __ballot_sync(0xffffffffu, pred);
    }

    // Phase 2: exact, in-order, 2-wide branch-lean survivor walk.
    float T = 1.0f;
    float accr = 0.0f, accg = 0.0f, accb = 0.0f;

    #pragma unroll
    for (int k = 0; k < NGRP; ++k) {
        unsigned mask = masks[k];
        const int gbase = base + k * 32;
        while (mask) {
            int j0 = gbase + (__ffs(mask) - 1);
            mask &= mask - 1;
            bool two = (mask != 0);
            int j1 = two ? (gbase + (__ffs(mask) - 1)) : j0;
            if (two) mask &= mask - 1;

            float4 A0 = g_A[j0], A1 = g_A[j1];
            float4 B0 = g_B[j0], B1 = g_B[j1];
            float2 C0 = g_C[j0], C1 = g_C[j1];

            float dx0 = px - A0.x, dy0 = py - A0.y;
            float dx1 = px - A1.x, dy1 = py - A1.y;
            float sg0 = 0.5f * (A0.z*dx0*dx0 + B0.x*dy0*dy0) + A0.w*dx0*dy0;
            float sg1 = 0.5f * (A1.z*dx1*dx1 + B1.x*dy1*dy1) + A1.w*dx1*dy1;
            float e0 = __expf(-sg0);
            float e1 = __expf(-sg1);

            float al0 = fminf(ALPHA_MAX, B0.y * e0);
            float al1 = fminf(ALPHA_MAX, B1.y * e1);
            // exact reference gate as selects (no divergent branches)
            al0 = ((sg0 > 0.0f) & (al0 >= ALPHA_MIN)) ? al0 : 0.0f;
            al1 = ((sg1 > 0.0f) & (al1 >= ALPHA_MIN) & two) ? al1 : 0.0f;

            float w0 = T * al0;
            accr = fmaf(w0, B0.z, accr);
            accg = fmaf(w0, B0.w, accg);
            accb = fmaf(w0, C0.x, accb);
            T *= (1.0f - al0);

            float w1 = T * al1;
            accr = fmaf(w1, B1.z, accr);
            accg = fmaf(w1, B1.w, accg);
            accb = fmaf(w1, C1.x, accb);
            T *= (1.0f - al1);
        }
    }

    smP[seg][yl * 8 + xl] = make_float4(accr, accg, accb, T);
    __syncthreads();

    // Fold the 8 segments front-to-back + background (threads 0..63).
    if (tid < 64) {
        float fr = 0.0f, fg = 0.0f, fb = 0.0f, fT = 1.0f;
        #pragma unroll
        for (int s = 0; s < NSEG; ++s) {
            float4 v = smP[s][tid];
            fr = fmaf(fT, v.x, fr);
            fg = fmaf(fT, v.y, fg);
            fb = fmaf(fT, v.z, fb);
            fT *= v.w;
        }
        const int pix = (ty0 + (tid >> 3)) * WIDTH + tx0 + (tid & 7);
        out[0 * HW + pix] = fmaf(background[0], fT, fr);
        out[1 * HW + pix] = fmaf(background[1], fT, fg);
        out[2 * HW + pix] = fmaf(background[2], fT, fb);
    }
}

// ---------------------------------------------------------------------------
extern "C" void kernel_launch(void* const* d_in, const int* in_sizes, int n_in,
                              void* d_out, int out_size)
{
    const float* means2d    = (const float*)d_in[0];
    const float* conics     = (const float*)d_in[1];
    const float* colors     = (const float*)d_in[2];
    const float* opacities  = (const float*)d_in[3];
    const float* depths     = (const float*)d_in[4];
    const float* background = (const float*)d_in[5];
    float* out = (float*)d_out;

    sort_scatter_kernel<<<N_GAUSS / 8, 256>>>(means2d, conics, colors, opacities, depths);
    dim3 grid(WIDTH / 8, HEIGHT / 8);
    render_fused_kernel<<<grid, 512>>>(background, out);
}